// round 15
// baseline (speedup 1.0000x reference)
#include <cuda_runtime.h>
#include <math.h>

// MaxNormPooling2D: quaternion max-norm 2x2 pooling, stride 2, VALID.
// Inputs: x0..x3 each (B=16, H=128, W=128, C=64) fp32, NHWC.
// Output: concatenated (out0..out3), each (16, 64, 64, 64) fp32.
//
// R10 (final): kernel is AT the roofline — minimal traffic (335.5 MB) at
// the measured ~6.0 TB/s achievable mixed-stream bandwidth = 53.3 us, which
// is exactly what every good config measures. This round keeps the best
// config (R9: float4 loads, 4 blocks/SM persistent single wave, index-carry
// argmax + L1-hit winner re-fetch, 55 regs / DRAM 75.7%) and explicitly
// front-batches all 16 window loads before any arithmetic to maximize
// MLP_p1 (request-train density), the only remaining micro-lever.

#define B_  16
#define H_  128
#define W_  128
#define C_  64
#define HO_ 64
#define WO_ 64

#define C4_ 16
#define NWORK_TOTAL (B_ * HO_ * WO_ * C4_)      // 1,048,576 float4 items
#define OUT_COMP_F4 (B_ * HO_ * WO_ * C_ / 4)   // 1,048,576

#define THREADS_ 256
#define NSM_     148
#define BLKS_PER_SM_ 4
#define GRID_    (NSM_ * BLKS_PER_SM_)           // 592 persistent blocks
#define STRIDE_  (GRID_ * THREADS_)              // 151,552

__global__ __launch_bounds__(THREADS_, BLKS_PER_SM_) void maxnorm_pool_kernel(
    const float4* __restrict__ x0,
    const float4* __restrict__ x1,
    const float4* __restrict__ x2,
    const float4* __restrict__ x3,
    float4* __restrict__ out)
{
    // scalar views for the winner re-fetch (L1 hits)
    const float* __restrict__ f0 = (const float*)x0;
    const float* __restrict__ f1 = (const float*)x1;
    const float* __restrict__ f2 = (const float*)x2;
    const float* __restrict__ f3 = (const float*)x3;

    for (int t = blockIdx.x * THREADS_ + threadIdx.x; t < NWORK_TOTAL; t += STRIDE_) {
        int c4  = t & (C4_ - 1);
        int pix = t >> 4;             // b*HO*WO + ho*WO + wo
        int wo  = pix & (WO_ - 1);
        int ho  = (pix >> 6) & (HO_ - 1);
        int b   = pix >> 12;

        int h0 = ho << 1;
        int w0 = wo << 1;

        // input index in float4 units: ((b*H + h)*W + w)*C4 + c4
        int base = ((b * H_ + h0) * W_ + w0) * C4_ + c4;
        // window positions row-major: (0,0),(0,1),(1,0),(1,1)
        int off0 = base;
        int off1 = base + C4_;
        int off2 = base + W_ * C4_;
        int off3 = base + W_ * C4_ + C4_;

        // ---- front-batched loads: all 16 LDG.128 issued before any FMA ----
        float4 a0_0 = x0[off0], a0_1 = x0[off1], a0_2 = x0[off2], a0_3 = x0[off3];
        float4 a1_0 = x1[off0], a1_1 = x1[off1], a1_2 = x1[off2], a1_3 = x1[off3];
        float4 a2_0 = x2[off0], a2_1 = x2[off1], a2_2 = x2[off2], a2_3 = x2[off3];
        float4 a3_0 = x3[off0], a3_1 = x3[off1], a3_2 = x3[off2], a3_3 = x3[off3];

        // best norm + best window index per component.
        // norms >= 0, bn = -1 => p=0 wins first -> first-max tie-break
        // (strict >), matching TF/argmax.
        float bnx = -1.f, bny = -1.f, bnz = -1.f, bnw = -1.f;
        int bix = 0, biy = 0, biz = 0, biw = 0;

#define EVAL_WIN(p, A0, A1, A2, A3)                                            \
        {                                                                      \
            /* sequential sum order x0^2+x1^2+x2^2+x3^2 then sqrt — matches */ \
            /* the reference's comparison domain for tie behavior. */          \
            float nx = sqrtf(A0.x*A0.x + A1.x*A1.x + A2.x*A2.x + A3.x*A3.x);   \
            float ny = sqrtf(A0.y*A0.y + A1.y*A1.y + A2.y*A2.y + A3.y*A3.y);   \
            float nz = sqrtf(A0.z*A0.z + A1.z*A1.z + A2.z*A2.z + A3.z*A3.z);   \
            float nw = sqrtf(A0.w*A0.w + A1.w*A1.w + A2.w*A2.w + A3.w*A3.w);   \
            if (nx > bnx) { bnx = nx; bix = p; }                               \
            if (ny > bny) { bny = ny; biy = p; }                               \
            if (nz > bnz) { bnz = nz; biz = p; }                               \
            if (nw > bnw) { bnw = nw; biw = p; }                               \
        }

        EVAL_WIN(0, a0_0, a1_0, a2_0, a3_0)
        EVAL_WIN(1, a0_1, a1_1, a2_1, a3_1)
        EVAL_WIN(2, a0_2, a1_2, a2_2, a3_2)
        EVAL_WIN(3, a0_3, a1_3, a2_3, a3_3)
#undef EVAL_WIN

        // Re-fetch the winning elements (same memory, unmodified -> exact
        // values; all L1 hits). Float offset of component c at window p:
        // (base + step(p)) * 4 + c.
        int sx = (base + (bix & 1) * C4_ + (bix >> 1) * (W_ * C4_)) * 4;
        int sy = (base + (biy & 1) * C4_ + (biy >> 1) * (W_ * C4_)) * 4 + 1;
        int sz = (base + (biz & 1) * C4_ + (biz >> 1) * (W_ * C4_)) * 4 + 2;
        int sw = (base + (biw & 1) * C4_ + (biw >> 1) * (W_ * C4_)) * 4 + 3;

        float4 o0, o1, o2, o3;
        o0.x = f0[sx]; o0.y = f0[sy]; o0.z = f0[sz]; o0.w = f0[sw];
        o1.x = f1[sx]; o1.y = f1[sy]; o1.z = f1[sz]; o1.w = f1[sw];
        o2.x = f2[sx]; o2.y = f2[sy]; o2.z = f2[sz]; o2.w = f2[sw];
        o3.x = f3[sx]; o3.y = f3[sy]; o3.z = f3[sz]; o3.w = f3[sw];

        int obase = pix * C4_ + c4;   // within one component, float4 units
        out[obase]                   = o0;
        out[obase +     OUT_COMP_F4] = o1;
        out[obase + 2 * OUT_COMP_F4] = o2;
        out[obase + 3 * OUT_COMP_F4] = o3;
    }
}

extern "C" void kernel_launch(void* const* d_in, const int* in_sizes, int n_in,
                              void* d_out, int out_size)
{
    const float4* x0 = (const float4*)d_in[0];
    const float4* x1 = (const float4*)d_in[1];
    const float4* x2 = (const float4*)d_in[2];
    const float4* x3 = (const float4*)d_in[3];
    float4* out = (float4*)d_out;

    maxnorm_pool_kernel<<<GRID_, THREADS_>>>(x0, x1, x2, x3, out);
}